// round 15
// baseline (speedup 1.0000x reference)
#include <cuda_runtime.h>
#include <cuda_fp16.h>
#include <cstdint>

// Problem: S=128, I=J=512, CM=256, C=D=32, CZ=128
// opm: PERSISTENT kernel, 148 CTAs x 512 threads; tile = 4i x 8j pairs (8192 tiles).
// Phase A: D[128m x 256n], K=128 (Ah·Bh). Phase B: Z[128cz x 32p], K=16x64 (Wh·Oh).
// Cross-tile pipelining: next tile's A/B staged in phase-B q=0/1 slots; next tile's
// Wo stages 0/1 staged in q=14/15 slots. Uniform 16 commits per tile.

// ---------------- smem layout (bytes) ----------------
#define A_RES     0                      // 2 A tiles [128][72] fp16 = 36864
#define B_BUF(b)  (36864 + (b) * 36864)  // 2 B tiles [256][72] fp16 (ends 110592)
#define OHI       110592                 // O [32p][1032k] fp16 = 66048 (ends 176640)
#define OSTRIDE   2064
#define WO_OFF    176640                 // 2 groups x 2 stages x 10240 (ends 217600)
#define GBUF_SZ   20480
#define STG_SZ    10240
#define WSTR      80
#define TSTRIDE   144
#define SMEM2     217600
#define NTILES    8192
#define NCTA      148
#define K1_SMEM   ((2*32*260 + 16*256) * 4)

// Pre-tiled globals (plain [row][64k] fp16 tiles):
__device__ __align__(256) __half g_A3[128 * 2 * 8192];
__device__ __align__(256) __half g_B3[64 * 2 * 16384];
__device__ __align__(256) __half g_Wo3[16 * 8192];

// ---------------- helpers ----------------
__device__ __forceinline__ uint32_t smem_u32(const void* p) {
    uint32_t a;
    asm("{ .reg .u64 t; cvta.to.shared.u64 t, %1; cvt.u32.u64 %0, t; }" : "=r"(a) : "l"(p));
    return a;
}
__device__ __forceinline__ void cp16(uint32_t smdst, const void* src) {
    asm volatile("cp.async.cg.shared.global [%0], [%1], 16;" :: "r"(smdst), "l"(src));
}
__device__ __forceinline__ void cp_commit() { asm volatile("cp.async.commit_group;"); }
template<int N> __device__ __forceinline__ void cp_wait() {
    asm volatile("cp.async.wait_group %0;" :: "n"(N));
}
__device__ __forceinline__ void barx(int id) {
    asm volatile("bar.sync %0, 256;" :: "r"(id) : "memory");
}
__device__ __forceinline__ void ldm_x4(uint32_t* r, uint32_t addr) {
    asm volatile("ldmatrix.sync.aligned.m8n8.x4.shared.b16 {%0,%1,%2,%3}, [%4];"
                 : "=r"(r[0]), "=r"(r[1]), "=r"(r[2]), "=r"(r[3]) : "r"(addr));
}
__device__ __forceinline__ void mma16816(float* d, const uint32_t* a, uint32_t b0, uint32_t b1) {
    asm volatile(
        "mma.sync.aligned.m16n8k16.row.col.f32.f16.f16.f32 "
        "{%0,%1,%2,%3}, {%4,%5,%6,%7}, {%8,%9}, {%0,%1,%2,%3};"
        : "+f"(d[0]), "+f"(d[1]), "+f"(d[2]), "+f"(d[3])
        : "r"(a[0]), "r"(a[1]), "r"(a[2]), "r"(a[3]), "r"(b0), "r"(b1));
}
__device__ __forceinline__ uint32_t packh2(float lo, float hi) {
    __half2 h = __floats2half2_rn(lo, hi);
    return *(uint32_t*)&h;
}
__device__ __forceinline__ uint32_t oswz(uint32_t col) {
    return col ^ (((col >> 6) & 7u) << 4);
}
__device__ __forceinline__ void stage_tile(uint32_t smdst, const __half* g,
                                           int rows, int t, int nthr) {
    const char* s = (const char*)g;
    for (int idx = t; idx < rows * 8; idx += nthr) {
        int r = idx >> 3, c = idx & 7;
        cp16(smdst + r * TSTRIDE + c * 16, s + r * 128 + c * 16);
    }
}
__device__ __forceinline__ void stage_w(uint32_t dst, int kt, int khalf, int gt) {
    const char* hi = (const char*)(g_Wo3 + (size_t)kt * 8192) + khalf * 64;
    #pragma unroll
    for (int idx = gt; idx < 512; idx += 256) {
        int r = idx >> 2, c = idx & 3;
        cp16(dst + r * WSTR + c * 16, hi + r * 128 + c * 16);
    }
}

// =====================================================================
// Kernel 0: Wo -> fp16 tiled global.
// =====================================================================
__global__ void wo_prep_kernel(const float* __restrict__ Wo) {
    int idx = blockIdx.x * 256 + threadIdx.x;      // 131072
    int cz = idx >> 10, k = idx & 1023;
    int kt = k >> 6, kk = k & 63;
    g_Wo3[kt * 8192 + cz * 64 + kk] = __float2half_rn(Wo[idx]);
}

// =====================================================================
// Kernel 1: LayerNorm + dual projection -> fp16 pre-tiled globals.
// =====================================================================
__global__ __launch_bounds__(256, 2)
void ln_proj_kernel(const float* __restrict__ x,
                    const float* __restrict__ nw,
                    const float* __restrict__ nb,
                    const float* __restrict__ Wa,
                    const float* __restrict__ Wb)
{
    extern __shared__ float sm[];
    float* Wa_s = sm;                 // [32][260]
    float* Wb_s = sm + 32 * 260;
    float* ln_s = sm + 2 * 32 * 260;  // [16][256]

    const int t = threadIdx.x, lane = t & 31, w = t >> 5;

    for (int idx = t; idx < 8192; idx += 256) {
        int c = idx >> 8, m = idx & 255;
        Wa_s[c * 260 + m] = Wa[idx];
        Wb_s[c * 260 + m] = Wb[idx];
    }

    const int r0 = blockIdx.x * 16 + w * 2;
    #pragma unroll
    for (int rr = 0; rr < 2; rr++) {
        const int row = r0 + rr;
        const float* xr = x + (size_t)row * 256;
        float v[8]; float s = 0.f, sq = 0.f;
        #pragma unroll
        for (int h = 0; h < 2; h++) {
            float4 x4 = *(const float4*)(xr + lane * 4 + 128 * h);
            v[h*4+0]=x4.x; v[h*4+1]=x4.y; v[h*4+2]=x4.z; v[h*4+3]=x4.w;
            s  += x4.x + x4.y + x4.z + x4.w;
            sq += x4.x*x4.x + x4.y*x4.y + x4.z*x4.z + x4.w*x4.w;
        }
        #pragma unroll
        for (int o = 16; o > 0; o >>= 1) {
            s  += __shfl_xor_sync(0xffffffffu, s,  o);
            sq += __shfl_xor_sync(0xffffffffu, sq, o);
        }
        float mu  = s * (1.f / 256.f);
        float var = sq * (1.f / 256.f) - mu * mu;
        float rs  = rsqrtf(var + 1e-5f);
        #pragma unroll
        for (int h = 0; h < 2; h++) {
            int m0 = lane * 4 + 128 * h;
            float4 w4 = *(const float4*)(nw + m0);
            float4 b4 = *(const float4*)(nb + m0);
            float* lp = ln_s + (w * 2 + rr) * 256 + m0;
            lp[0] = (v[h*4+0]-mu)*rs*w4.x + b4.x;
            lp[1] = (v[h*4+1]-mu)*rs*w4.y + b4.y;
            lp[2] = (v[h*4+2]-mu)*rs*w4.z + b4.z;
            lp[3] = (v[h*4+3]-mu)*rs*w4.w + b4.w;
        }
    }
    __syncthreads();

    float accA[2] = {0.f, 0.f}, accB[2] = {0.f, 0.f};
    const float* lr0 = ln_s + (w * 2) * 256;
    const float* lr1 = lr0 + 256;
    const float* war = Wa_s + lane * 260;
    const float* wbr = Wb_s + lane * 260;
    #pragma unroll 8
    for (int m4 = 0; m4 < 64; m4++) {
        float4 wa4 = *(const float4*)(war + m4 * 4);
        float4 wb4 = *(const float4*)(wbr + m4 * 4);
        float4 l0  = *(const float4*)(lr0 + m4 * 4);
        float4 l1  = *(const float4*)(lr1 + m4 * 4);
        accA[0] = fmaf(l0.x, wa4.x, accA[0]); accA[0] = fmaf(l0.y, wa4.y, accA[0]);
        accA[0] = fmaf(l0.z, wa4.z, accA[0]); accA[0] = fmaf(l0.w, wa4.w, accA[0]);
        accB[0] = fmaf(l0.x, wb4.x, accB[0]); accB[0] = fmaf(l0.y, wb4.y, accB[0]);
        accB[0] = fmaf(l0.z, wb4.z, accB[0]); accB[0] = fmaf(l0.w, wb4.w, accB[0]);
        accA[1] = fmaf(l1.x, wa4.x, accA[1]); accA[1] = fmaf(l1.y, wa4.y, accA[1]);
        accA[1] = fmaf(l1.z, wa4.z, accA[1]); accA[1] = fmaf(l1.w, wa4.w, accA[1]);
        accB[1] = fmaf(l1.x, wb4.x, accB[1]); accB[1] = fmaf(l1.y, wb4.y, accB[1]);
        accB[1] = fmaf(l1.z, wb4.z, accB[1]); accB[1] = fmaf(l1.w, wb4.w, accB[1]);
    }

    #pragma unroll
    for (int rr = 0; rr < 2; rr++) {
        const int row = r0 + rr;
        __half ah = __float2half_rn(accA[rr]);
        __half bh = __float2half_rn(accB[rr]);
        const int ss = row >> 9, ij = row & 511;
        const int kts = ss >> 6, kk = ss & 63;
        {   // A: Ah at tile kts
            int it = ij >> 2, m = (ij & 3) * 32 + lane;
            g_A3[(size_t)(it * 2 + kts) * 8192 + m * 64 + kk] = ah;
        }
        {   // B: Bh at tile kts
            int jt = ij >> 3, n = (ij & 7) * 32 + lane;
            g_B3[(size_t)(jt * 2 + kts) * 16384 + n * 64 + kk] = bh;
        }
    }
}

// =====================================================================
// Kernel 2: persistent fused OPM + projection, 148 CTAs x 512 threads.
// =====================================================================
__global__ __launch_bounds__(512, 1)
void opm_kernel(const float* __restrict__ bo, float* __restrict__ out)
{
    extern __shared__ char smc[];
    const uint32_t sb = smem_u32(smc);
    const int t = threadIdx.x, lane = t & 31, wid = t >> 5;
    const int g  = wid >> 3;              // phase-B group (kt parity)
    const int gt = t & 255;
    const int wm = wid & 3, wn = (wid >> 2) & 3;   // phase A 4x4 warp grid
    const uint32_t lrow = (uint32_t)(lane & 15) * TSTRIDE;
    const uint32_t lcol = (uint32_t)(lane >> 4) * 16;
    const int wg  = wid & 7;
    const int czt = wg * 16;
    const uint32_t WB   = sb + WO_OFF + g * GBUF_SZ;
    const uint32_t wrow = (uint32_t)(czt + (lane & 15)) * WSTR + (uint32_t)(lane >> 4) * 16;
    const uint32_t orow = (uint32_t)(lane & 15) * OSTRIDE;

    // ---- first-tile prologue. Commits: c0={A0,B0} c1={A1,B1} c2=Wst0 c3=Wst1 ----
    {
        const int tile0 = blockIdx.x;
        const int jt0 = tile0 & 63, it0 = tile0 >> 6;
        const __half* A0 = g_A3 + (size_t)(it0 * 2) * 8192;
        const __half* B0 = g_B3 + (size_t)(jt0 * 2) * 16384;
        stage_tile(sb + A_RES,         A0,         128, t, 512);
        stage_tile(sb + B_BUF(0),      B0,         256, t, 512);
        cp_commit();                                                // c0
        stage_tile(sb + A_RES + 18432, A0 + 8192,  128, t, 512);
        stage_tile(sb + B_BUF(1),      B0 + 16384, 256, t, 512);
        cp_commit();                                                // c1
        stage_w(WB,          g, 0, gt);  cp_commit();               // c2
        stage_w(WB + STG_SZ, g, 1, gt);  cp_commit();               // c3
    }

    bool first = true;
    for (int tile = blockIdx.x; tile < NTILES; tile += NCTA) {
        const int jt = tile & 63, it = tile >> 6;
        const bool more = (tile + NCTA) < NTILES;
        const int ntile = tile + NCTA;
        const __half* nA = g_A3 + (size_t)((ntile >> 6) * 2) * 8192;
        const __half* nB = g_B3 + (size_t)((ntile & 63) * 2) * 16384;

        // ---- Phase A: kt 0..1 (A/B prefetched during previous tile's phase B) ----
        float acc[2][8][4];
        #pragma unroll
        for (int mt = 0; mt < 2; mt++)
            #pragma unroll
            for (int nt = 0; nt < 8; nt++)
                #pragma unroll
                for (int e = 0; e < 4; e++) acc[mt][nt][e] = 0.f;

        #pragma unroll 1
        for (int kt = 0; kt < 2; kt++) {
            // waits: first tile kt0 wait<3> (c0 done); otherwise wait<2>
            // (steady state: leaves the 2 next-tile-Wo commits q=14/15 outstanding)
            if (first && kt == 0) cp_wait<3>(); else cp_wait<2>();
            __syncthreads();
            const uint32_t aB = sb + A_RES + (uint32_t)kt * 18432
                              + (uint32_t)(wm * 32) * TSTRIDE + lrow + lcol;
            const uint32_t bB = sb + B_BUF(kt)
                              + (uint32_t)(wn * 64) * TSTRIDE + lrow + lcol;
            #pragma unroll
            for (int k16 = 0; k16 < 4; k16++) {
                uint32_t A4[2][4], B4[4][4];
                #pragma unroll
                for (int mt = 0; mt < 2; mt++) ldm_x4(A4[mt], aB + mt * 16 * TSTRIDE + k16 * 32);
                #pragma unroll
                for (int bt = 0; bt < 4; bt++) ldm_x4(B4[bt], bB + bt * 16 * TSTRIDE + k16 * 32);
                #pragma unroll
                for (int mt = 0; mt < 2; mt++)
                    #pragma unroll
                    for (int bt = 0; bt < 4; bt++) {
                        mma16816(acc[mt][bt*2],   A4[mt], B4[bt][0], B4[bt][2]);
                        mma16816(acc[mt][bt*2+1], A4[mt], B4[bt][1], B4[bt][3]);
                    }
            }
            __syncthreads();
        }

        // ---- Epilogue: accums -> O smem (own region; fp16, XOR-swizzled) ----
        {
            const int m0 = wm * 32, n0 = wn * 64;
            const int mr = lane >> 2, nc = (lane & 3) * 2;
            #pragma unroll
            for (int mt = 0; mt < 2; mt++)
                #pragma unroll
                for (int nt = 0; nt < 8; nt++) {
                    #pragma unroll
                    for (int h = 0; h < 2; h++) {
                        int m = m0 + mt * 16 + mr + h * 8;
                        int n = n0 + nt * 8 + nc;
                        float f0 = acc[mt][nt][2*h]   * (1.f / 128.f);
                        float f1 = acc[mt][nt][2*h+1] * (1.f / 128.f);
                        uint32_t hv = packh2(f0, f1);
                        int p = (m >> 5) * 8 + (n >> 5);
                        uint32_t col = oswz((uint32_t)(((m & 31) * 32 + (n & 31)) * 2));
                        asm volatile("st.shared.b32 [%0], %1;"
                                     :: "r"(sb + OHI + (uint32_t)(p * OSTRIDE) + col), "r"(hv)
                                     : "memory");
                    }
                }
        }
        __syncthreads();

        // ---- Phase B: 16 stages; group g: kt = g+2*(q>>1), kh = q&1.
        //      Staging slots: q0/q1 -> next tile A/B; q<=13 -> Wo q+2;
        //      q14/q15 -> next tile Wo stages 0/1. Uniform 1 commit per q. ----
        float z[4][4];
        #pragma unroll
        for (int nt = 0; nt < 4; nt++)
            #pragma unroll
            for (int e = 0; e < 4; e++) z[nt][e] = 0.f;

        #pragma unroll 1
        for (int q = 0; q < 16; q++) {
            const int kt = g + ((q >> 1) << 1);
            const int kh = q & 1;
            cp_wait<1>();       // positional: stage q's commit (2 back) complete
            barx(1 + g);
            const uint32_t ws = WB + (uint32_t)(q & 1) * STG_SZ;
            #pragma unroll
            for (int k16 = 0; k16 < 2; k16++) {
                uint32_t Whi[4], OhA[4], OhB[4];
                ldm_x4(Whi, ws + wrow + k16 * 32);
                const uint32_t ocol = oswz((uint32_t)(kt * 128 + kh * 64 + k16 * 32)
                                           + (uint32_t)(lane >> 4) * 16);
                const uint32_t ob = sb + OHI + orow + ocol;
                ldm_x4(OhA, ob);
                ldm_x4(OhB, ob + 16 * OSTRIDE);
                mma16816(z[0], Whi, OhA[0], OhA[2]); mma16816(z[1], Whi, OhA[1], OhA[3]);
                mma16816(z[2], Whi, OhB[0], OhB[2]); mma16816(z[3], Whi, OhB[1], OhB[3]);
            }
            barx(1 + g);        // group done reading buf (q&1) before overwrite
            if (q == 0 && more) {
                stage_tile(sb + A_RES,    nA,         128, t, 512);
                stage_tile(sb + B_BUF(0), nB,         256, t, 512);
            } else if (q == 1 && more) {
                stage_tile(sb + A_RES + 18432, nA + 8192,  128, t, 512);
                stage_tile(sb + B_BUF(1),      nB + 16384, 256, t, 512);
            }
            {
                const int q2 = q + 2;
                if (q2 < 16) {
                    stage_w(WB + (uint32_t)(q & 1) * STG_SZ,
                            g + ((q2 >> 1) << 1), q2 & 1, gt);
                } else if (more) {
                    const int q2m = q2 & 15;   // 0 or 1: next tile's stages
                    stage_w(WB + (uint32_t)(q & 1) * STG_SZ,
                            g + ((q2m >> 1) << 1), q2m & 1, gt);
                }
            }
            cp_commit();        // exactly one commit per q (maybe empty)
        }

        // ---- reduce group partials (zs in dead O region) + writeout ----
        __syncthreads();
        float* zs = (float*)(smc + OHI);   // [32][132] floats
        {
            const int mr = lane >> 2, nc = (lane & 3) * 2;
            if (g == 1) {
                #pragma unroll
                for (int nt = 0; nt < 4; nt++)
                    #pragma unroll
                    for (int e = 0; e < 4; e++) {
                        int cz = czt + mr + (e >> 1) * 8;
                        int pr = nt * 8 + nc + (e & 1);
                        zs[pr * 132 + cz] = z[nt][e];
                    }
            }
            __syncthreads();
            if (g == 0) {
                #pragma unroll
                for (int nt = 0; nt < 4; nt++)
                    #pragma unroll
                    for (int e = 0; e < 4; e++) {
                        int cz = czt + mr + (e >> 1) * 8;
                        int pr = nt * 8 + nc + (e & 1);
                        zs[pr * 132 + cz] += z[nt][e];
                    }
            }
        }
        __syncthreads();
        #pragma unroll
        for (int qq = 0; qq < 8; qq++) {
            int idx = qq * 512 + t;
            int pr = idx >> 7, cz = idx & 127;
            out[((it * 4 + (pr >> 3)) * 512 + jt * 8 + (pr & 7)) * 128 + cz]
                = zs[pr * 132 + cz] + bo[cz];
        }
        first = false;
    }
}

extern "C" void kernel_launch(void* const* d_in, const int* in_sizes, int n_in,
                              void* d_out, int out_size) {
    const float* x  = (const float*)d_in[0];
    const float* nw = (const float*)d_in[1];
    const float* nb = (const float*)d_in[2];
    const float* Wa = (const float*)d_in[3];
    const float* Wb = (const float*)d_in[4];
    const float* Wo = (const float*)d_in[5];
    const float* bo = (const float*)d_in[6];
    float* out = (float*)d_out;

    cudaFuncSetAttribute(ln_proj_kernel, cudaFuncAttributeMaxDynamicSharedMemorySize, K1_SMEM);
    cudaFuncSetAttribute(opm_kernel,     cudaFuncAttributeMaxDynamicSharedMemorySize, SMEM2);

    wo_prep_kernel<<<512, 256>>>(Wo);
    ln_proj_kernel<<<65536 / 16, 256, K1_SMEM>>>(x, nw, nb, Wa, Wb);
    opm_kernel<<<NCTA, 512, SMEM2>>>(bo, out);
}

// round 16
// speedup vs baseline: 1.1146x; 1.1146x over previous
#include <cuda_runtime.h>
#include <cuda_fp16.h>
#include <cstdint>

// Problem: S=128, I=J=512, CM=256, C=D=32, CZ=128
// opm CTA = 4i x 8j pairs; grid (64 jt, 128 it); 512 threads. Pure fp16 (round-12 best).
// k1: fused LN + tensor-core dual projection (128 rows/block, 512 blocks, occ 2).

// ---------------- opm smem layout (bytes) — round 12 ----------------
#define A_RES     0          // 2 resident A tiles: [128][72] fp16 x2 = 36864
#define B_BUF(b)  (36864 + (b) * 36864)   // 2 x [256][72] fp16  (ends 110592)
#define OHI       0          // O hi [32p][1032k] fp16 (overlaps phase-A bufs; sequential)
#define OSTRIDE   2064
#define WO_OFF    110592
#define GBUF_SZ   20480      // per group: 2 stages x 10240
#define STG_SZ    10240
#define WSTR      80
#define TSTRIDE   144
#define SMEM2     151552
// ---------------- k1 smem layout ----------------
#define W_OFF     0          // Wab [64][264h] = 33792 B
#define LNS_OFF   33792      // ln  [128][264h] = 67584 B
#define LSTR      528        // bytes per row (264 halfs); 33x16B odd -> ldm conflict-free
#define K1_SMEM   101376

// Pre-tiled globals (plain [row][64k] fp16 tiles):
__device__ __align__(256) __half g_A3[128 * 2 * 8192];
__device__ __align__(256) __half g_B3[64 * 2 * 16384];
__device__ __align__(256) __half g_Wo3[16 * 8192];
__device__ __align__(256) __half g_Wab[64 * 256];   // rows 0-31 Wa, 32-63 Wb; [c][m]

// ---------------- helpers ----------------
__device__ __forceinline__ uint32_t smem_u32(const void* p) {
    uint32_t a;
    asm("{ .reg .u64 t; cvta.to.shared.u64 t, %1; cvt.u32.u64 %0, t; }" : "=r"(a) : "l"(p));
    return a;
}
__device__ __forceinline__ void cp16(uint32_t smdst, const void* src) {
    asm volatile("cp.async.cg.shared.global [%0], [%1], 16;" :: "r"(smdst), "l"(src));
}
__device__ __forceinline__ void cp_commit() { asm volatile("cp.async.commit_group;"); }
template<int N> __device__ __forceinline__ void cp_wait() {
    asm volatile("cp.async.wait_group %0;" :: "n"(N));
}
__device__ __forceinline__ void barx(int id) {
    asm volatile("bar.sync %0, 256;" :: "r"(id) : "memory");
}
__device__ __forceinline__ void ldm_x4(uint32_t* r, uint32_t addr) {
    asm volatile("ldmatrix.sync.aligned.m8n8.x4.shared.b16 {%0,%1,%2,%3}, [%4];"
                 : "=r"(r[0]), "=r"(r[1]), "=r"(r[2]), "=r"(r[3]) : "r"(addr));
}
__device__ __forceinline__ void mma16816(float* d, const uint32_t* a, uint32_t b0, uint32_t b1) {
    asm volatile(
        "mma.sync.aligned.m16n8k16.row.col.f32.f16.f16.f32 "
        "{%0,%1,%2,%3}, {%4,%5,%6,%7}, {%8,%9}, {%0,%1,%2,%3};"
        : "+f"(d[0]), "+f"(d[1]), "+f"(d[2]), "+f"(d[3])
        : "r"(a[0]), "r"(a[1]), "r"(a[2]), "r"(a[3]), "r"(b0), "r"(b1));
}
__device__ __forceinline__ uint32_t packh2(float lo, float hi) {  // lo -> low half
    __half2 h = __floats2half2_rn(lo, hi);
    return *(uint32_t*)&h;
}
__device__ __forceinline__ uint32_t oswz(uint32_t col) {
    return col ^ (((col >> 6) & 7u) << 4);
}
__device__ __forceinline__ void stage_tile(uint32_t smdst, const __half* g,
                                           int rows, int t, int nthr) {
    const char* s = (const char*)g;
    for (int idx = t; idx < rows * 8; idx += nthr) {
        int r = idx >> 3, c = idx & 7;
        cp16(smdst + r * TSTRIDE + c * 16, s + r * 128 + c * 16);
    }
}
__device__ __forceinline__ void stage_w(uint32_t dst, int kt, int khalf, int gt) {
    const char* hi = (const char*)(g_Wo3 + (size_t)kt * 8192) + khalf * 64;
    #pragma unroll
    for (int idx = gt; idx < 512; idx += 256) {
        int r = idx >> 2, c = idx & 3;
        cp16(dst + r * WSTR + c * 16, hi + r * 128 + c * 16);
    }
}

// =====================================================================
// Kernel 0a: Wo -> fp16 tiled global.
// =====================================================================
__global__ void wo_prep_kernel(const float* __restrict__ Wo) {
    int idx = blockIdx.x * 256 + threadIdx.x;      // 131072
    int cz = idx >> 10, k = idx & 1023;
    int kt = k >> 6, kk = k & 63;
    g_Wo3[kt * 8192 + cz * 64 + kk] = __float2half_rn(Wo[idx]);
}
// =====================================================================
// Kernel 0b: Wa|Wb -> fp16 combined [64][256].
// =====================================================================
__global__ void wab_prep_kernel(const float* __restrict__ Wa,
                                const float* __restrict__ Wb) {
    int idx = blockIdx.x * 256 + threadIdx.x;      // 16384
    int c = idx >> 8, m = idx & 255;
    float v = (c < 32) ? Wa[c * 256 + m] : Wb[(c - 32) * 256 + m];
    g_Wab[idx] = __float2half_rn(v);
}

// =====================================================================
// Kernel 1: fused LN + tensor-core dual projection.
// 256 threads; block = 128 rows; 512 blocks; occ 2.
// =====================================================================
__global__ __launch_bounds__(256, 2)
void ln_proj_kernel(const float* __restrict__ x,
                    const float* __restrict__ nw,
                    const float* __restrict__ nb)
{
    extern __shared__ char smc[];
    const uint32_t sb = smem_u32(smc);
    const int t = threadIdx.x, lane = t & 31, wid = t >> 5;
    const int blk = blockIdx.x;

    // stage Wab [64][256] fp16 -> W_OFF with LSTR rows
    for (int idx = t; idx < 2048; idx += 256) {
        int r = idx >> 5, c = idx & 31;
        cp16(sb + W_OFF + r * LSTR + c * 16, (const char*)g_Wab + r * 512 + c * 16);
    }
    cp_commit();

    // LN: warp owns rows wid*16 .. +15; hoisted norm weights
    float4 w40 = *(const float4*)(nw + lane * 4);
    float4 w41 = *(const float4*)(nw + lane * 4 + 128);
    float4 b40 = *(const float4*)(nb + lane * 4);
    float4 b41 = *(const float4*)(nb + lane * 4 + 128);
    #pragma unroll 2
    for (int rr = 0; rr < 16; rr++) {
        const int r = wid * 16 + rr;
        const float* xr = x + ((size_t)blk * 128 + r) * 256;
        float4 x0 = *(const float4*)(xr + lane * 4);
        float4 x1 = *(const float4*)(xr + lane * 4 + 128);
        float s  = x0.x + x0.y + x0.z + x0.w + x1.x + x1.y + x1.z + x1.w;
        float sq = x0.x*x0.x + x0.y*x0.y + x0.z*x0.z + x0.w*x0.w
                 + x1.x*x1.x + x1.y*x1.y + x1.z*x1.z + x1.w*x1.w;
        #pragma unroll
        for (int o = 16; o > 0; o >>= 1) {
            s  += __shfl_xor_sync(0xffffffffu, s,  o);
            sq += __shfl_xor_sync(0xffffffffu, sq, o);
        }
        float mu  = s * (1.f / 256.f);
        float var = sq * (1.f / 256.f) - mu * mu;
        float rs  = rsqrtf(var + 1e-5f);
        uint32_t p0 = packh2((x0.x-mu)*rs*w40.x + b40.x, (x0.y-mu)*rs*w40.y + b40.y);
        uint32_t p1 = packh2((x0.z-mu)*rs*w40.z + b40.z, (x0.w-mu)*rs*w40.w + b40.w);
        uint32_t p2 = packh2((x1.x-mu)*rs*w41.x + b41.x, (x1.y-mu)*rs*w41.y + b41.y);
        uint32_t p3 = packh2((x1.z-mu)*rs*w41.z + b41.z, (x1.w-mu)*rs*w41.w + b41.w);
        uint32_t a0 = sb + LNS_OFF + (uint32_t)r * LSTR + (uint32_t)lane * 8;
        asm volatile("st.shared.v2.b32 [%0], {%1,%2};" :: "r"(a0),       "r"(p0), "r"(p1) : "memory");
        asm volatile("st.shared.v2.b32 [%0], {%1,%2};" :: "r"(a0 + 256), "r"(p2), "r"(p3) : "memory");
    }
    cp_wait<0>();
    __syncthreads();

    // mma: 8 warps (wm 0..3 x wn 0..1), warp tile 32m x 32n, K=256
    const int wm = wid & 3, wn = wid >> 2;
    const uint32_t lrow = (uint32_t)(lane & 15) * LSTR;
    const uint32_t lcol = (uint32_t)(lane >> 4) * 16;
    const uint32_t aB = sb + LNS_OFF + (uint32_t)(wm * 32) * LSTR + lrow + lcol;
    const uint32_t bB = sb + W_OFF   + (uint32_t)(wn * 32) * LSTR + lrow + lcol;
    float acc[2][4][4];
    #pragma unroll
    for (int mt = 0; mt < 2; mt++)
        #pragma unroll
        for (int nt = 0; nt < 4; nt++)
            #pragma unroll
            for (int e = 0; e < 4; e++) acc[mt][nt][e] = 0.f;

    #pragma unroll
    for (int k16 = 0; k16 < 16; k16++) {
        uint32_t A4[2][4], B4[2][4];
        #pragma unroll
        for (int mt = 0; mt < 2; mt++) ldm_x4(A4[mt], aB + mt * 16 * LSTR + k16 * 32);
        #pragma unroll
        for (int bt = 0; bt < 2; bt++) ldm_x4(B4[bt], bB + bt * 16 * LSTR + k16 * 32);
        #pragma unroll
        for (int mt = 0; mt < 2; mt++)
            #pragma unroll
            for (int bt = 0; bt < 2; bt++) {
                mma16816(acc[mt][bt*2],   A4[mt], B4[bt][0], B4[bt][2]);
                mma16816(acc[mt][bt*2+1], A4[mt], B4[bt][1], B4[bt][3]);
            }
    }

    // epilogue: scatter fragments to tiled globals (wn=0 -> A, wn=1 -> B)
    {
        const int ss = blk >> 2, kts = ss >> 6, kk = ss & 63;
        const int ijb = (blk & 3) * 128;
        const int mr = lane >> 2, nc = (lane & 3) * 2;
        #pragma unroll
        for (int mt = 0; mt < 2; mt++)
            #pragma unroll
            for (int nt = 0; nt < 4; nt++)
                #pragma unroll
                for (int e = 0; e < 4; e++) {
                    int rl = wm * 32 + mt * 16 + mr + (e >> 1) * 8;
                    int c  = wn * 32 + nt * 8 + nc + (e & 1);
                    __half v = __float2half_rn(acc[mt][nt][e]);
                    int ij = ijb + rl;
                    if (wn == 0) {
                        g_A3[(size_t)((ij >> 2) * 2 + kts) * 8192
                             + ((ij & 3) * 32 + c) * 64 + kk] = v;
                    } else {
                        g_B3[(size_t)((ij >> 3) * 2 + kts) * 16384
                             + ((ij & 7) * 32 + (c - 32)) * 64 + kk] = v;
                    }
                }
    }
}

// =====================================================================
// Kernel 2: fused OPM + projection, 512 threads, pure fp16 (round 12).
// =====================================================================
__global__ __launch_bounds__(512, 1)
void opm_kernel(const float* __restrict__ bo, float* __restrict__ out)
{
    extern __shared__ char smc[];
    const uint32_t sb = smem_u32(smc);
    const int t = threadIdx.x, lane = t & 31, wid = t >> 5;
    const int jt = blockIdx.x, it = blockIdx.y;
    const int g  = wid >> 3;
    const int gt = t & 255;

    const __half* Abase = g_A3 + (size_t)(it * 2) * 8192;
    const __half* Bbase = g_B3 + (size_t)(jt * 2) * 16384;

    // prologue. Commits: c0={A0,A1,B0} c1={B1} c2=Wst0 c3=Wst1
    stage_tile(sb + A_RES,         Abase,         128, t, 512);
    stage_tile(sb + A_RES + 18432, Abase + 8192,  128, t, 512);
    stage_tile(sb + B_BUF(0),      Bbase,         256, t, 512);
    cp_commit();
    stage_tile(sb + B_BUF(1),      Bbase + 16384, 256, t, 512);
    cp_commit();
    {
        uint32_t WB = sb + WO_OFF + g * GBUF_SZ;
        stage_w(WB,          g, 0, gt);  cp_commit();
        stage_w(WB + STG_SZ, g, 1, gt);  cp_commit();
    }

    // Phase A: kt 0..1
    const int wm = wid & 3, wn = wid >> 2;
    const uint32_t lrow = (uint32_t)(lane & 15) * TSTRIDE;
    const uint32_t lcol = (uint32_t)(lane >> 4) * 16;
    float acc[2][8][4];
    #pragma unroll
    for (int mt = 0; mt < 2; mt++)
        #pragma unroll
        for (int nt = 0; nt < 8; nt++)
            #pragma unroll
            for (int e = 0; e < 4; e++) acc[mt][nt][e] = 0.f;

    #pragma unroll 1
    for (int kt = 0; kt < 2; kt++) {
        if (kt == 0) cp_wait<3>(); else cp_wait<2>();
        __syncthreads();
        const uint32_t aB = sb + A_RES + (uint32_t)kt * 18432
                          + (uint32_t)(wm * 32) * TSTRIDE + lrow + lcol;
        const uint32_t bB = sb + B_BUF(kt)
                          + (uint32_t)(wn * 64) * TSTRIDE + lrow + lcol;
        #pragma unroll
        for (int k16 = 0; k16 < 4; k16++) {
            uint32_t A4[2][4], B4[4][4];
            #pragma unroll
            for (int mt = 0; mt < 2; mt++) ldm_x4(A4[mt], aB + mt * 16 * TSTRIDE + k16 * 32);
            #pragma unroll
            for (int bt = 0; bt < 4; bt++) ldm_x4(B4[bt], bB + bt * 16 * TSTRIDE + k16 * 32);
            #pragma unroll
            for (int mt = 0; mt < 2; mt++)
                #pragma unroll
                for (int bt = 0; bt < 4; bt++) {
                    mma16816(acc[mt][bt*2],   A4[mt], B4[bt][0], B4[bt][2]);
                    mma16816(acc[mt][bt*2+1], A4[mt], B4[bt][1], B4[bt][3]);
                }
        }
        __syncthreads();
    }

    // Epilogue: accums -> O smem
    {
        const int m0 = wm * 32, n0 = wn * 64;
        const int mr = lane >> 2, nc = (lane & 3) * 2;
        #pragma unroll
        for (int mt = 0; mt < 2; mt++)
            #pragma unroll
            for (int nt = 0; nt < 8; nt++) {
                #pragma unroll
                for (int h = 0; h < 2; h++) {
                    int m = m0 + mt * 16 + mr + h * 8;
                    int n = n0 + nt * 8 + nc;
                    float f0 = acc[mt][nt][2*h]   * (1.f / 128.f);
                    float f1 = acc[mt][nt][2*h+1] * (1.f / 128.f);
                    uint32_t hv = packh2(f0, f1);
                    int p = (m >> 5) * 8 + (n >> 5);
                    uint32_t col = oswz((uint32_t)(((m & 31) * 32 + (n & 31)) * 2));
                    asm volatile("st.shared.b32 [%0], %1;"
                                 :: "r"(sb + OHI + (uint32_t)(p * OSTRIDE) + col), "r"(hv)
                                 : "memory");
                }
            }
    }
    __syncthreads();

    // Phase B
    float z[4][4];
    #pragma unroll
    for (int nt = 0; nt < 4; nt++)
        #pragma unroll
        for (int e = 0; e < 4; e++) z[nt][e] = 0.f;

    const int wg  = wid & 7;
    const int czt = wg * 16;
    const uint32_t WB   = sb + WO_OFF + g * GBUF_SZ;
    const uint32_t wrow = (uint32_t)(czt + (lane & 15)) * WSTR + (uint32_t)(lane >> 4) * 16;
    const uint32_t orow = (uint32_t)(lane & 15) * OSTRIDE;

    #pragma unroll 1
    for (int q = 0; q < 16; q++) {
        const int kt = g + ((q >> 1) << 1);
        const int kh = q & 1;
        cp_wait<1>();
        barx(1 + g);
        const uint32_t ws = WB + (q & 1) * STG_SZ;
        #pragma unroll
        for (int k16 = 0; k16 < 2; k16++) {
            uint32_t Whi[4], OhA[4], OhB[4];
            ldm_x4(Whi, ws + wrow + k16 * 32);
            const uint32_t ocol = oswz((uint32_t)(kt * 128 + kh * 64 + k16 * 32)
                                       + (uint32_t)(lane >> 4) * 16);
            const uint32_t ob = sb + OHI + orow + ocol;
            ldm_x4(OhA, ob);
            ldm_x4(OhB, ob + 16 * OSTRIDE);
            mma16816(z[0], Whi, OhA[0], OhA[2]); mma16816(z[1], Whi, OhA[1], OhA[3]);
            mma16816(z[2], Whi, OhB[0], OhB[2]); mma16816(z[3], Whi, OhB[1], OhB[3]);
        }
        barx(1 + g);
        if (q + 2 < 16) {
            const int q2 = q + 2;
            stage_w(WB + (q & 1) * STG_SZ, g + ((q2 >> 1) << 1), q2 & 1, gt);
        }
        cp_commit();
    }

    // reduce group partials + writeout
    __syncthreads();
    float* zs = (float*)(smc + WO_OFF);
    {
        const int mr = lane >> 2, nc = (lane & 3) * 2;
        if (g == 1) {
            #pragma unroll
            for (int nt = 0; nt < 4; nt++)
                #pragma unroll
                for (int e = 0; e < 4; e++) {
                    int cz = czt + mr + (e >> 1) * 8;
                    int pr = nt * 8 + nc + (e & 1);
                    zs[pr * 132 + cz] = z[nt][e];
                }
        }
        __syncthreads();
        if (g == 0) {
            #pragma unroll
            for (int nt = 0; nt < 4; nt++)
                #pragma unroll
                for (int e = 0; e < 4; e++) {
                    int cz = czt + mr + (e >> 1) * 8;
                    int pr = nt * 8 + nc + (e & 1);
                    zs[pr * 132 + cz] += z[nt][e];
                }
        }
    }
    __syncthreads();
    #pragma unroll
    for (int q = 0; q < 8; q++) {
        int idx = q * 512 + t;
        int pr = idx >> 7, cz = idx & 127;
        out[((it * 4 + (pr >> 3)) * 512 + jt * 8 + (pr & 7)) * 128 + cz]
            = zs[pr * 132 + cz] + bo[cz];
    }
}

extern "C" void kernel_launch(void* const* d_in, const int* in_sizes, int n_in,
                              void* d_out, int out_size) {
    const float* x  = (const float*)d_in[0];
    const float* nw = (const float*)d_in[1];
    const float* nb = (const float*)d_in[2];
    const float* Wa = (const float*)d_in[3];
    const float* Wb = (const float*)d_in[4];
    const float* Wo = (const float*)d_in[5];
    const float* bo = (const float*)d_in[6];
    float* out = (float*)d_out;

    cudaFuncSetAttribute(ln_proj_kernel, cudaFuncAttributeMaxDynamicSharedMemorySize, K1_SMEM);
    cudaFuncSetAttribute(opm_kernel,     cudaFuncAttributeMaxDynamicSharedMemorySize, SMEM2);

    wo_prep_kernel<<<512, 256>>>(Wo);
    wab_prep_kernel<<<64, 256>>>(Wa, Wb);
    ln_proj_kernel<<<512, 256, K1_SMEM>>>(x, nw, nb);
    opm_kernel<<<dim3(64, 128), 512, SMEM2>>>(bo, out);
}

// round 17
// speedup vs baseline: 1.1608x; 1.0414x over previous
#include <cuda_runtime.h>
#include <cuda_fp16.h>
#include <cstdint>

// Problem: S=128, I=J=512, CM=256, C=D=32, CZ=128
// opm CTA = 4i x 8j pairs; grid (64 jt, 128 it); 1024 threads (32 warps). Pure fp16.
// Phase A: D[128m x 256n], K=128; 32 warps, tile 32x32.
// Phase B: Z[128cz x 32p], K=16kt x 64k; 4 kt-parity groups x 8 warps.
// k1: fused LN + tensor-core dual projection (round 16).

// ---------------- opm smem layout (bytes) ----------------
#define A_RES     0                       // 2 A tiles [128][72] fp16 = 36864
#define B_BUF(b)  (36864 + (b) * 36864)   // 2 B tiles [256][72] fp16 (ends 110592)
#define OHI       0                       // O [32p][1032k] fp16 (overlaps A/B; sequential)
#define OSTRIDE   2064
#define WO_OFF    110592                  // 4 groups x 2 stages x 10240 = 81920 (ends 192512)
#define GBUF_SZ   20480
#define STG_SZ    10240
#define WSTR      80
#define TSTRIDE   144
#define SMEM2     192512
// ---------------- k1 smem layout ----------------
#define W_OFF     0          // Wab [64][264h] = 33792 B
#define LNS_OFF   33792      // ln  [128][264h] = 67584 B
#define LSTR      528
#define K1_SMEM   101376

// Pre-tiled globals (plain [row][64k] fp16 tiles):
__device__ __align__(256) __half g_A3[128 * 2 * 8192];
__device__ __align__(256) __half g_B3[64 * 2 * 16384];
__device__ __align__(256) __half g_Wo3[16 * 8192];
__device__ __align__(256) __half g_Wab[64 * 256];   // rows 0-31 Wa, 32-63 Wb; [c][m]

// ---------------- helpers ----------------
__device__ __forceinline__ uint32_t smem_u32(const void* p) {
    uint32_t a;
    asm("{ .reg .u64 t; cvta.to.shared.u64 t, %1; cvt.u32.u64 %0, t; }" : "=r"(a) : "l"(p));
    return a;
}
__device__ __forceinline__ void cp16(uint32_t smdst, const void* src) {
    asm volatile("cp.async.cg.shared.global [%0], [%1], 16;" :: "r"(smdst), "l"(src));
}
__device__ __forceinline__ void cp_commit() { asm volatile("cp.async.commit_group;"); }
template<int N> __device__ __forceinline__ void cp_wait() {
    asm volatile("cp.async.wait_group %0;" :: "n"(N));
}
__device__ __forceinline__ void barx(int id) {
    asm volatile("bar.sync %0, 256;" :: "r"(id) : "memory");
}
__device__ __forceinline__ void ldm_x4(uint32_t* r, uint32_t addr) {
    asm volatile("ldmatrix.sync.aligned.m8n8.x4.shared.b16 {%0,%1,%2,%3}, [%4];"
                 : "=r"(r[0]), "=r"(r[1]), "=r"(r[2]), "=r"(r[3]) : "r"(addr));
}
__device__ __forceinline__ void mma16816(float* d, const uint32_t* a, uint32_t b0, uint32_t b1) {
    asm volatile(
        "mma.sync.aligned.m16n8k16.row.col.f32.f16.f16.f32 "
        "{%0,%1,%2,%3}, {%4,%5,%6,%7}, {%8,%9}, {%0,%1,%2,%3};"
        : "+f"(d[0]), "+f"(d[1]), "+f"(d[2]), "+f"(d[3])
        : "r"(a[0]), "r"(a[1]), "r"(a[2]), "r"(a[3]), "r"(b0), "r"(b1));
}
__device__ __forceinline__ uint32_t packh2(float lo, float hi) {
    __half2 h = __floats2half2_rn(lo, hi);
    return *(uint32_t*)&h;
}
__device__ __forceinline__ uint32_t oswz(uint32_t col) {
    return col ^ (((col >> 6) & 7u) << 4);
}
__device__ __forceinline__ void stage_tile(uint32_t smdst, const __half* g,
                                           int rows, int t, int nthr) {
    const char* s = (const char*)g;
    for (int idx = t; idx < rows * 8; idx += nthr) {
        int r = idx >> 3, c = idx & 7;
        cp16(smdst + r * TSTRIDE + c * 16, s + r * 128 + c * 16);
    }
}
__device__ __forceinline__ void stage_w(uint32_t dst, int kt, int khalf, int gt) {
    const char* hi = (const char*)(g_Wo3 + (size_t)kt * 8192) + khalf * 64;
    #pragma unroll
    for (int idx = gt; idx < 512; idx += 256) {
        int r = idx >> 2, c = idx & 3;
        cp16(dst + r * WSTR + c * 16, hi + r * 128 + c * 16);
    }
}

// =====================================================================
// Kernel 0a: Wo -> fp16 tiled global.
// =====================================================================
__global__ void wo_prep_kernel(const float* __restrict__ Wo) {
    int idx = blockIdx.x * 256 + threadIdx.x;      // 131072
    int cz = idx >> 10, k = idx & 1023;
    int kt = k >> 6, kk = k & 63;
    g_Wo3[kt * 8192 + cz * 64 + kk] = __float2half_rn(Wo[idx]);
}
// =====================================================================
// Kernel 0b: Wa|Wb -> fp16 combined [64][256].
// =====================================================================
__global__ void wab_prep_kernel(const float* __restrict__ Wa,
                                const float* __restrict__ Wb) {
    int idx = blockIdx.x * 256 + threadIdx.x;      // 16384
    int c = idx >> 8, m = idx & 255;
    float v = (c < 32) ? Wa[c * 256 + m] : Wb[(c - 32) * 256 + m];
    g_Wab[idx] = __float2half_rn(v);
}

// =====================================================================
// Kernel 1: fused LN + tensor-core dual projection (round 16).
// =====================================================================
__global__ __launch_bounds__(256, 2)
void ln_proj_kernel(const float* __restrict__ x,
                    const float* __restrict__ nw,
                    const float* __restrict__ nb)
{
    extern __shared__ char smc[];
    const uint32_t sb = smem_u32(smc);
    const int t = threadIdx.x, lane = t & 31, wid = t >> 5;
    const int blk = blockIdx.x;

    for (int idx = t; idx < 2048; idx += 256) {
        int r = idx >> 5, c = idx & 31;
        cp16(sb + W_OFF + r * LSTR + c * 16, (const char*)g_Wab + r * 512 + c * 16);
    }
    cp_commit();

    float4 w40 = *(const float4*)(nw + lane * 4);
    float4 w41 = *(const float4*)(nw + lane * 4 + 128);
    float4 b40 = *(const float4*)(nb + lane * 4);
    float4 b41 = *(const float4*)(nb + lane * 4 + 128);
    #pragma unroll 2
    for (int rr = 0; rr < 16; rr++) {
        const int r = wid * 16 + rr;
        const float* xr = x + ((size_t)blk * 128 + r) * 256;
        float4 x0 = *(const float4*)(xr + lane * 4);
        float4 x1 = *(const float4*)(xr + lane * 4 + 128);
        float s  = x0.x + x0.y + x0.z + x0.w + x1.x + x1.y + x1.z + x1.w;
        float sq = x0.x*x0.x + x0.y*x0.y + x0.z*x0.z + x0.w*x0.w
                 + x1.x*x1.x + x1.y*x1.y + x1.z*x1.z + x1.w*x1.w;
        #pragma unroll
        for (int o = 16; o > 0; o >>= 1) {
            s  += __shfl_xor_sync(0xffffffffu, s,  o);
            sq += __shfl_xor_sync(0xffffffffu, sq, o);
        }
        float mu  = s * (1.f / 256.f);
        float var = sq * (1.f / 256.f) - mu * mu;
        float rs  = rsqrtf(var + 1e-5f);
        uint32_t p0 = packh2((x0.x-mu)*rs*w40.x + b40.x, (x0.y-mu)*rs*w40.y + b40.y);
        uint32_t p1 = packh2((x0.z-mu)*rs*w40.z + b40.z, (x0.w-mu)*rs*w40.w + b40.w);
        uint32_t p2 = packh2((x1.x-mu)*rs*w41.x + b41.x, (x1.y-mu)*rs*w41.y + b41.y);
        uint32_t p3 = packh2((x1.z-mu)*rs*w41.z + b41.z, (x1.w-mu)*rs*w41.w + b41.w);
        uint32_t a0 = sb + LNS_OFF + (uint32_t)r * LSTR + (uint32_t)lane * 8;
        asm volatile("st.shared.v2.b32 [%0], {%1,%2};" :: "r"(a0),       "r"(p0), "r"(p1) : "memory");
        asm volatile("st.shared.v2.b32 [%0], {%1,%2};" :: "r"(a0 + 256), "r"(p2), "r"(p3) : "memory");
    }
    cp_wait<0>();
    __syncthreads();

    const int wm = wid & 3, wn = wid >> 2;
    const uint32_t lrow = (uint32_t)(lane & 15) * LSTR;
    const uint32_t lcol = (uint32_t)(lane >> 4) * 16;
    const uint32_t aB = sb + LNS_OFF + (uint32_t)(wm * 32) * LSTR + lrow + lcol;
    const uint32_t bB = sb + W_OFF   + (uint32_t)(wn * 32) * LSTR + lrow + lcol;
    float acc[2][4][4];
    #pragma unroll
    for (int mt = 0; mt < 2; mt++)
        #pragma unroll
        for (int nt = 0; nt < 4; nt++)
            #pragma unroll
            for (int e = 0; e < 4; e++) acc[mt][nt][e] = 0.f;

    #pragma unroll
    for (int k16 = 0; k16 < 16; k16++) {
        uint32_t A4[2][4], B4[2][4];
        #pragma unroll
        for (int mt = 0; mt < 2; mt++) ldm_x4(A4[mt], aB + mt * 16 * LSTR + k16 * 32);
        #pragma unroll
        for (int bt = 0; bt < 2; bt++) ldm_x4(B4[bt], bB + bt * 16 * LSTR + k16 * 32);
        #pragma unroll
        for (int mt = 0; mt < 2; mt++)
            #pragma unroll
            for (int bt = 0; bt < 2; bt++) {
                mma16816(acc[mt][bt*2],   A4[mt], B4[bt][0], B4[bt][2]);
                mma16816(acc[mt][bt*2+1], A4[mt], B4[bt][1], B4[bt][3]);
            }
    }

    {
        const int ss = blk >> 2, kts = ss >> 6, kk = ss & 63;
        const int ijb = (blk & 3) * 128;
        const int mr = lane >> 2, nc = (lane & 3) * 2;
        #pragma unroll
        for (int mt = 0; mt < 2; mt++)
            #pragma unroll
            for (int nt = 0; nt < 4; nt++)
                #pragma unroll
                for (int e = 0; e < 4; e++) {
                    int rl = wm * 32 + mt * 16 + mr + (e >> 1) * 8;
                    int c  = wn * 32 + nt * 8 + nc + (e & 1);
                    __half v = __float2half_rn(acc[mt][nt][e]);
                    int ij = ijb + rl;
                    if (wn == 0) {
                        g_A3[(size_t)((ij >> 2) * 2 + kts) * 8192
                             + ((ij & 3) * 32 + c) * 64 + kk] = v;
                    } else {
                        g_B3[(size_t)((ij >> 3) * 2 + kts) * 16384
                             + ((ij & 7) * 32 + (c - 32)) * 64 + kk] = v;
                    }
                }
    }
}

// =====================================================================
// Kernel 2: fused OPM + projection, 1024 threads (32 warps), pure fp16.
// =====================================================================
__global__ __launch_bounds__(1024, 1)
void opm_kernel(const float* __restrict__ bo, float* __restrict__ out)
{
    extern __shared__ char smc[];
    const uint32_t sb = smem_u32(smc);
    const int t = threadIdx.x, lane = t & 31, wid = t >> 5;
    const int jt = blockIdx.x, it = blockIdx.y;
    const int g  = wid >> 3;              // phase-B group: kt mod 4
    const int gt = t & 255;

    const __half* Abase = g_A3 + (size_t)(it * 2) * 8192;
    const __half* Bbase = g_B3 + (size_t)(jt * 2) * 16384;

    // ---- prologue. Commits: c0={A0,A1,B0} c1={B1} c2=Wst0 c3=Wst1 ----
    stage_tile(sb + A_RES,         Abase,         128, t, 1024);
    stage_tile(sb + A_RES + 18432, Abase + 8192,  128, t, 1024);
    stage_tile(sb + B_BUF(0),      Bbase,         256, t, 1024);
    cp_commit();                                                    // c0
    stage_tile(sb + B_BUF(1),      Bbase + 16384, 256, t, 1024);
    cp_commit();                                                    // c1
    {   // group g: stage q=0 (kt=g, k0-31), q=1 (kt=g, k32-63)
        uint32_t WB = sb + WO_OFF + g * GBUF_SZ;
        stage_w(WB,          g, 0, gt);  cp_commit();               // c2
        stage_w(WB + STG_SZ, g, 1, gt);  cp_commit();               // c3
    }

    // ---- Phase A: 32 warps, 4m x 8n grid, warp tile 32x32; kt 0..1 ----
    const int wm = wid & 3, wn = wid >> 2;
    const uint32_t lrow = (uint32_t)(lane & 15) * TSTRIDE;
    const uint32_t lcol = (uint32_t)(lane >> 4) * 16;
    float acc[2][4][4];
    #pragma unroll
    for (int mt = 0; mt < 2; mt++)
        #pragma unroll
        for (int nt = 0; nt < 4; nt++)
            #pragma unroll
            for (int e = 0; e < 4; e++) acc[mt][nt][e] = 0.f;

    #pragma unroll 1
    for (int kt = 0; kt < 2; kt++) {
        if (kt == 0) cp_wait<3>(); else cp_wait<2>();
        __syncthreads();
        const uint32_t aB = sb + A_RES + (uint32_t)kt * 18432
                          + (uint32_t)(wm * 32) * TSTRIDE + lrow + lcol;
        const uint32_t bB = sb + B_BUF(kt)
                          + (uint32_t)(wn * 32) * TSTRIDE + lrow + lcol;
        #pragma unroll
        for (int k16 = 0; k16 < 4; k16++) {
            uint32_t A4[2][4], B4[2][4];
            #pragma unroll
            for (int mt = 0; mt < 2; mt++) ldm_x4(A4[mt], aB + mt * 16 * TSTRIDE + k16 * 32);
            #pragma unroll
            for (int bt = 0; bt < 2; bt++) ldm_x4(B4[bt], bB + bt * 16 * TSTRIDE + k16 * 32);
            #pragma unroll
            for (int mt = 0; mt < 2; mt++)
                #pragma unroll
                for (int bt = 0; bt < 2; bt++) {
                    mma16816(acc[mt][bt*2],   A4[mt], B4[bt][0], B4[bt][2]);
                    mma16816(acc[mt][bt*2+1], A4[mt], B4[bt][1], B4[bt][3]);
                }
        }
        __syncthreads();
    }

    // ---- Epilogue: accums -> O smem (fp16, XOR-swizzled cols) ----
    {
        const int m0 = wm * 32, n0 = wn * 32;
        const int mr = lane >> 2, nc = (lane & 3) * 2;
        #pragma unroll
        for (int mt = 0; mt < 2; mt++)
            #pragma unroll
            for (int nt = 0; nt < 4; nt++) {
                #pragma unroll
                for (int h = 0; h < 2; h++) {
                    int m = m0 + mt * 16 + mr + h * 8;
                    int n = n0 + nt * 8 + nc;
                    float f0 = acc[mt][nt][2*h]   * (1.f / 128.f);
                    float f1 = acc[mt][nt][2*h+1] * (1.f / 128.f);
                    uint32_t hv = packh2(f0, f1);
                    int p = (m >> 5) * 8 + (n >> 5);
                    uint32_t col = oswz((uint32_t)(((m & 31) * 32 + (n & 31)) * 2));
                    asm volatile("st.shared.b32 [%0], %1;"
                                 :: "r"(sb + OHI + (uint32_t)(p * OSTRIDE) + col), "r"(hv)
                                 : "memory");
                }
            }
    }
    __syncthreads();

    // ---- Phase B: 4 groups; group g: 8 stages q, kt = g + 4*(q>>1), kh = q&1 ----
    float z[4][4];
    #pragma unroll
    for (int nt = 0; nt < 4; nt++)
        #pragma unroll
        for (int e = 0; e < 4; e++) z[nt][e] = 0.f;

    const int wg  = wid & 7;
    const int czt = wg * 16;
    const uint32_t WB   = sb + WO_OFF + g * GBUF_SZ;
    const uint32_t wrow = (uint32_t)(czt + (lane & 15)) * WSTR + (uint32_t)(lane >> 4) * 16;
    const uint32_t orow = (uint32_t)(lane & 15) * OSTRIDE;

    #pragma unroll 1
    for (int q = 0; q < 8; q++) {
        const int kt = g + ((q >> 1) << 2);
        const int kh = q & 1;
        cp_wait<1>();       // uniform commits: stage q landed
        barx(1 + g);
        const uint32_t ws = WB + (q & 1) * STG_SZ;
        #pragma unroll
        for (int k16 = 0; k16 < 2; k16++) {
            uint32_t Whi[4], OhA[4], OhB[4];
            ldm_x4(Whi, ws + wrow + k16 * 32);
            const uint32_t ocol = oswz((uint32_t)(kt * 128 + kh * 64 + k16 * 32)
                                       + (uint32_t)(lane >> 4) * 16);
            const uint32_t ob = sb + OHI + orow + ocol;
            ldm_x4(OhA, ob);
            ldm_x4(OhB, ob + 16 * OSTRIDE);
            mma16816(z[0], Whi, OhA[0], OhA[2]); mma16816(z[1], Whi, OhA[1], OhA[3]);
            mma16816(z[2], Whi, OhB[0], OhB[2]); mma16816(z[3], Whi, OhB[1], OhB[3]);
        }
        barx(1 + g);        // group done reading buf (q&1) before restage
        if (q + 2 < 8) {
            const int q2 = q + 2;
            stage_w(WB + (q & 1) * STG_SZ, g + ((q2 >> 1) << 2), q2 & 1, gt);
        }
        cp_commit();        // uniform group count (maybe empty)
    }

    // ---- 4-way partial sum via dead Wo region + writeout ----
    __syncthreads();
    float* zsb = (float*)(smc + WO_OFF);   // 4 buffers of [32p][132cz]
    {
        float* zs = zsb + g * 4224;
        const int mr = lane >> 2, nc = (lane & 3) * 2;
        #pragma unroll
        for (int nt = 0; nt < 4; nt++)
            #pragma unroll
            for (int e = 0; e < 4; e++) {
                int cz = czt + mr + (e >> 1) * 8;
                int pr = nt * 8 + nc + (e & 1);
                zs[pr * 132 + cz] = z[nt][e];
            }
    }
    __syncthreads();
    #pragma unroll
    for (int q = 0; q < 4; q++) {
        int idx = q * 1024 + t;
        int pr = idx >> 7, cz = idx & 127;
        int o = pr * 132 + cz;
        float v = zsb[o] + zsb[4224 + o] + zsb[8448 + o] + zsb[12672 + o];
        out[((it * 4 + (pr >> 3)) * 512 + jt * 8 + (pr & 7)) * 128 + cz] = v + bo[cz];
    }
}

extern "C" void kernel_launch(void* const* d_in, const int* in_sizes, int n_in,
                              void* d_out, int out_size) {
    const float* x  = (const float*)d_in[0];
    const float* nw = (const float*)d_in[1];
    const float* nb = (const float*)d_in[2];
    const float* Wa = (const float*)d_in[3];
    const float* Wb = (const float*)d_in[4];
    const float* Wo = (const float*)d_in[5];
    const float* bo = (const float*)d_in[6];
    float* out = (float*)d_out;

    cudaFuncSetAttribute(ln_proj_kernel, cudaFuncAttributeMaxDynamicSharedMemorySize, K1_SMEM);
    cudaFuncSetAttribute(opm_kernel,     cudaFuncAttributeMaxDynamicSharedMemorySize, SMEM2);

    wo_prep_kernel<<<512, 256>>>(Wo);
    wab_prep_kernel<<<64, 256>>>(Wa, Wb);
    ln_proj_kernel<<<512, 256, K1_SMEM>>>(x, nw, nb);
    opm_kernel<<<dim3(64, 128), 1024, SMEM2>>>(bo, out);
}